// round 2
// baseline (speedup 1.0000x reference)
#include <cuda_runtime.h>

// PointPillarsBEV, Round 2:
//  K1 (primary): persistent zero-fill of 268MB canvas, triggers PDL early.
//  K2 (secondary, PDL): persistent PFN compute -> feats scratch (overlapped with K1),
//      then cudaGridDependencySynchronize(), then atomic scatter.

#define NPTS 32
#define DIMS 10
#define CH 64
#define BEV_H 512
#define BEV_W 512
#define HWSZ (BEV_H * BEV_W)
#define P_PER_B 12000
#define BATCH 4
#define PILLARS_TOTAL (BATCH * P_PER_B)

#define ZGRID 296            // 2 blocks/SM -> all resident wave 1, trigger fires at t~0
#define PFN_BLOCKS 444       // persistent
#define WPB 8
#define NWARPS (PFN_BLOCKS * WPB)   // 3552
#define SHS 36               // padded shared row stride (floats), 16B-aligned rows

typedef unsigned long long ull;

__device__ float g_feats[PILLARS_TOTAL * CH];   // 12.3MB stash, mostly L2-resident

__device__ __forceinline__ ull pk2(float a, float b) {
    ull r; asm("mov.b64 %0, {%1, %2};" : "=l"(r) : "f"(a), "f"(b)); return r;
}
__device__ __forceinline__ void fma2(ull& acc, ull x, ull w) {
    asm("fma.rn.f32x2 %0, %1, %2, %0;" : "+l"(acc) : "l"(x), "l"(w));
}
__device__ __forceinline__ float2 up2(ull v) {
    float2 r; asm("mov.b64 {%0, %1}, %2;" : "=f"(r.x), "=f"(r.y) : "l"(v)); return r;
}

__global__ void __launch_bounds__(256) zero_out_kernel(float4* __restrict__ out, int n4) {
#if __CUDA_ARCH__ >= 900
    cudaTriggerProgrammaticLaunchCompletion();
#endif
    int stride = gridDim.x * blockDim.x;
    for (int i = blockIdx.x * blockDim.x + threadIdx.x; i < n4; i += stride)
        out[i] = make_float4(0.f, 0.f, 0.f, 0.f);
}

__global__ void __launch_bounds__(256) pfn_scatter_kernel(
    const float* __restrict__ pillars,   // (B, P, NPTS, DIMS)
    const int*   __restrict__ coords,    // (B, P, 2)  [y, x]
    const float* __restrict__ w,         // (DIMS, CH)
    const float* __restrict__ bias,      // (CH)
    float*       __restrict__ out)       // (B, CH, H, W)
{
    __shared__ __align__(16) float sh[WPB][DIMS * SHS];
    __shared__ __align__(16) ull shw[2][DIMS][32];   // packed (w,w) per half/dim/lane
    __shared__ float shb[CH];

    const int tid  = threadIdx.x;
    const int warp = tid >> 5;
    const int lane = tid & 31;
    const int gwarp = blockIdx.x * WPB + warp;

    // Build packed weight table once per block (640 entries)
    for (int i = tid; i < DIMS * CH; i += 256) {
        int d = i >> 6, c = i & 63;
        float v = __ldg(&w[d * CH + c]);
        shw[c >> 5][d][c & 31] = pk2(v, v);
    }
    if (tid < CH) shb[tid] = __ldg(&bias[tid]);
    __syncthreads();

    // Per-lane staging map: element j = k*32 + lane of the pillar -> sh[d][n]
    int soff[DIMS];
#pragma unroll
    for (int k = 0; k < DIMS; k++) {
        int j = k * 32 + lane;
        int n = j / DIMS, dd = j - n * DIMS;
        soff[k] = dd * SHS + n;
    }

    // ---------------- compute phase (independent of canvas) ----------------
    int p = gwarp;
    float r[DIMS];
    if (p < PILLARS_TOTAL) {
        const float* src = pillars + (size_t)p * (NPTS * DIMS);
#pragma unroll
        for (int k = 0; k < DIMS; k++) r[k] = __ldg(&src[k * 32 + lane]);
    }
    for (; p < PILLARS_TOTAL; p += NWARPS) {
        __syncwarp();
#pragma unroll
        for (int k = 0; k < DIMS; k++) sh[warp][soff[k]] = r[k];
        __syncwarp();
        // prefetch next pillar while computing this one
        int pn = p + NWARPS;
        if (pn < PILLARS_TOTAL) {
            const float* src = pillars + (size_t)pn * (NPTS * DIMS);
#pragma unroll
            for (int k = 0; k < DIMS; k++) r[k] = __ldg(&src[k * 32 + lane]);
        }

#pragma unroll
        for (int half = 0; half < 2; half++) {
            ull wv[DIMS];
#pragma unroll
            for (int d = 0; d < DIMS; d++) wv[d] = shw[half][d][lane];
            float bb = shb[half * 32 + lane];
            ull bd = pk2(bb, bb);
            float m = 0.f;   // max(relu(v)) == max(0, max(v))
#pragma unroll
            for (int n0 = 0; n0 < NPTS; n0 += 8) {
                ull a0 = bd, a1 = bd, a2 = bd, a3 = bd;
#pragma unroll
                for (int d = 0; d < DIMS; d++) {
                    const float* base = &sh[warp][d * SHS + n0];
                    ulonglong2 x0 = *reinterpret_cast<const ulonglong2*>(base);
                    ulonglong2 x1 = *reinterpret_cast<const ulonglong2*>(base + 4);
                    fma2(a0, x0.x, wv[d]);
                    fma2(a1, x0.y, wv[d]);
                    fma2(a2, x1.x, wv[d]);
                    fma2(a3, x1.y, wv[d]);
                }
                float2 v0 = up2(a0), v1 = up2(a1), v2 = up2(a2), v3 = up2(a3);
                m = fmaxf(m, fmaxf(fmaxf(fmaxf(v0.x, v0.y), fmaxf(v1.x, v1.y)),
                                   fmaxf(fmaxf(v2.x, v2.y), fmaxf(v3.x, v3.y))));
            }
            g_feats[p * CH + half * 32 + lane] = m;
        }
    }

    // ---------------- wait for canvas zeroing, then scatter ----------------
#if __CUDA_ARCH__ >= 900
    cudaGridDependencySynchronize();
#endif
    for (int q = gwarp; q < PILLARS_TOTAL; q += NWARPS) {
        int b = q / P_PER_B;
        int y = __ldg(&coords[2 * q]);
        int x = __ldg(&coords[2 * q + 1]);
        float f0 = g_feats[q * CH + lane];
        float f1 = g_feats[q * CH + 32 + lane];
        float* o = out + (size_t)b * CH * HWSZ + (size_t)y * BEV_W + x;
        atomicAdd(o + (size_t)lane * HWSZ, f0);
        atomicAdd(o + (size_t)(lane + 32) * HWSZ, f1);
    }
}

extern "C" void kernel_launch(void* const* d_in, const int* in_sizes, int n_in,
                              void* d_out, int out_size) {
    const float* pillars = (const float*)d_in[0];
    const int*   coords  = (const int*)d_in[1];
    const float* w       = (const float*)d_in[2];
    const float* bias    = (const float*)d_in[3];
    float* out = (float*)d_out;

    int n4 = out_size / 4;
    zero_out_kernel<<<ZGRID, 256>>>((float4*)out, n4);

    cudaLaunchConfig_t cfg = {};
    cfg.gridDim = dim3(PFN_BLOCKS);
    cfg.blockDim = dim3(256);
    cfg.dynamicSmemBytes = 0;
    cfg.stream = 0;
    cudaLaunchAttribute attr[1];
    attr[0].id = cudaLaunchAttributeProgrammaticStreamSerialization;
    attr[0].val.programmaticStreamSerializationAllowed = 1;
    cfg.attrs = attr;
    cfg.numAttrs = 1;
    cudaLaunchKernelEx(&cfg, pfn_scatter_kernel, pillars, coords, w, bias, out);
}